// round 3
// baseline (speedup 1.0000x reference)
#include <cuda_runtime.h>

#define Bn  2
#define Sn  192
#define Dn  128
#define DIN 1024
#define BSn (Bn*Sn)                       // 384 rows
#define SZo ((long)Bn*Sn*Sn*Sn)           // 14,155,776 elements per output tensor

// ---- scratch (device globals: allocation-free contract) ----
__device__ float g_mlp[3*BSn*Dn];         // p, sh, st        (576 KB)
__device__ float g_wz[BSn*Dn*Dn];         // wz / u scratch   (25.2 MB)
__device__ float g_t [BSn*Sn*Dn];         // t  / v scratch   (37.7 MB)

// ============================================================================
// MLP: C = leaky_relu(x @ W + b), 64x64 tiles, K=1024. grid(6,2,3)
// ============================================================================
__global__ __launch_bounds__(256) void mlp_kernel(
    const float* __restrict__ x,
    const float* __restrict__ W0, const float* __restrict__ b0,
    const float* __restrict__ W1, const float* __restrict__ b1,
    const float* __restrict__ W2, const float* __restrict__ b2)
{
    const int mt = blockIdx.x, nt = blockIdx.y, w = blockIdx.z;
    const float* W    = (w == 0) ? W0 : (w == 1) ? W1 : W2;
    const float* bias = (w == 0) ? b0 : (w == 1) ? b1 : b2;
    float* C = g_mlp + (long)w * BSn * Dn;

    __shared__ float As[64][17];
    __shared__ float Bs[16][65];
    const int tid = threadIdx.x;
    const int tx = tid & 15, ty = tid >> 4;
    const int m0 = mt * 64, n0 = nt * 64;
    float acc[4][4] = {};

    for (int k0 = 0; k0 < DIN; k0 += 16) {
        {   // A tile [64 x 16]
            int mm = tid >> 2, kk = (tid & 3) << 2;
            float4 v = *(const float4*)(x + (long)(m0 + mm) * DIN + k0 + kk);
            As[mm][kk] = v.x; As[mm][kk+1] = v.y; As[mm][kk+2] = v.z; As[mm][kk+3] = v.w;
        }
        {   // B tile [16 x 64] (NN)
            int kk = tid >> 4, nn = (tid & 15) << 2;
            float4 v = *(const float4*)(W + (long)(k0 + kk) * Dn + n0 + nn);
            Bs[kk][nn] = v.x; Bs[kk][nn+1] = v.y; Bs[kk][nn+2] = v.z; Bs[kk][nn+3] = v.w;
        }
        __syncthreads();
        #pragma unroll
        for (int kk = 0; kk < 16; kk++) {
            float a[4], b[4];
            #pragma unroll
            for (int r = 0; r < 4; r++) a[r] = As[ty*4 + r][kk];
            #pragma unroll
            for (int c = 0; c < 4; c++) b[c] = Bs[kk][tx + 16*c];
            #pragma unroll
            for (int r = 0; r < 4; r++)
                #pragma unroll
                for (int c = 0; c < 4; c++) acc[r][c] = fmaf(a[r], b[c], acc[r][c]);
        }
        __syncthreads();
    }
    #pragma unroll
    for (int r = 0; r < 4; r++) {
        int m = m0 + ty*4 + r;
        #pragma unroll
        for (int c = 0; c < 4; c++) {
            int n = n0 + tx + 16*c;
            float v = acc[r][c] + bias[n];
            v = (v > 0.f) ? v : 0.1f * v;
            C[(long)m * Dn + n] = v;
        }
    }
}

// ============================================================================
// Generic batched GEMM: C[m,n] = sum_c A[m,c] * B[m? n,c or c,n]
//   grid: (M/64, N/64, batch).  K fixed = 128.
//   A base = A + (z / aDiv) * aStride ; B base = B + z * bStride ; C base = C + z * cStride
//   bT = 0 : NN  (B[c*ldb + n]),  bT = 1 : NT  (B[n*ldb + c])
// ============================================================================
__global__ __launch_bounds__(256) void gemm_kernel(
    const float* __restrict__ A, const float* __restrict__ Bm, float* __restrict__ C,
    int lda, int ldb, int ldc,
    int aDiv, long aStride, long bStride, long cStride, int bT)
{
    const int mt = blockIdx.x, nt = blockIdx.y, z = blockIdx.z;
    const float* Ab = A + (long)(z / aDiv) * aStride;
    const float* Bb = Bm + (long)z * bStride;
    float* Cb = C + (long)z * cStride;
    const int m0 = mt * 64, n0 = nt * 64;

    __shared__ float As[64][17];
    __shared__ float Bs[16][65];
    const int tid = threadIdx.x;
    const int tx = tid & 15, ty = tid >> 4;
    float acc[4][4] = {};

    for (int k0 = 0; k0 < 128; k0 += 16) {
        {
            int mm = tid >> 2, kk = (tid & 3) << 2;
            float4 v = *(const float4*)(Ab + (long)(m0 + mm) * lda + k0 + kk);
            As[mm][kk] = v.x; As[mm][kk+1] = v.y; As[mm][kk+2] = v.z; As[mm][kk+3] = v.w;
        }
        if (!bT) {
            int kk = tid >> 4, nn = (tid & 15) << 2;
            float4 v = *(const float4*)(Bb + (long)(k0 + kk) * ldb + n0 + nn);
            Bs[kk][nn] = v.x; Bs[kk][nn+1] = v.y; Bs[kk][nn+2] = v.z; Bs[kk][nn+3] = v.w;
        } else {
            int nn = tid >> 2, kk = (tid & 3) << 2;
            float4 v = *(const float4*)(Bb + (long)(n0 + nn) * ldb + k0 + kk);
            Bs[kk][nn] = v.x; Bs[kk+1][nn] = v.y; Bs[kk+2][nn] = v.z; Bs[kk+3][nn] = v.w;
        }
        __syncthreads();
        #pragma unroll
        for (int kk = 0; kk < 16; kk++) {
            float a[4], b[4];
            #pragma unroll
            for (int r = 0; r < 4; r++) a[r] = As[ty*4 + r][kk];
            #pragma unroll
            for (int c = 0; c < 4; c++) b[c] = Bs[kk][tx + 16*c];
            #pragma unroll
            for (int r = 0; r < 4; r++)
                #pragma unroll
                for (int c = 0; c < 4; c++) acc[r][c] = fmaf(a[r], b[c], acc[r][c]);
        }
        __syncthreads();
    }
    #pragma unroll
    for (int r = 0; r < 4; r++) {
        int m = m0 + ty*4 + r;
        #pragma unroll
        for (int c = 0; c < 4; c++)
            Cb[(long)m * ldc + n0 + tx + 16*c] = acc[r][c];
    }
}

// ============================================================================
// Output GEMM (stage B2): s[q][m,n] = sum_k A[q][m,k] * Y[b][n,k]   (NT)
//   M = N = Sn, K = 128, batch q in [0, BSn). Writes to Out + q*Sn*Sn.
//   sym = 1: compute only upper tiles, write value + mirror (triu + triu(1).T)
//   sym = 0: full write.
// ============================================================================
__global__ __launch_bounds__(256) void gemm_out_kernel(
    const float* __restrict__ A, const float* __restrict__ Y,
    float* __restrict__ Out, int sym)
{
    const int bx = blockIdx.x, by = blockIdx.y, q = blockIdx.z;
    if (sym && bx > by) return;
    const float* Ab = A + (long)q * (Sn * Dn);
    const float* Bb = Y + (long)(q / Sn) * (Sn * Dn);
    float* Ob = Out + (long)q * (Sn * Sn);
    const int m0 = bx * 64, n0 = by * 64;

    __shared__ float As[64][17];
    __shared__ float Bs[16][65];
    __shared__ float Cs[64][65];
    const int tid = threadIdx.x;
    const int tx = tid & 15, ty = tid >> 4;
    float acc[4][4] = {};

    for (int k0 = 0; k0 < 128; k0 += 16) {
        {
            int mm = tid >> 2, kk = (tid & 3) << 2;
            float4 v = *(const float4*)(Ab + (long)(m0 + mm) * Dn + k0 + kk);
            As[mm][kk] = v.x; As[mm][kk+1] = v.y; As[mm][kk+2] = v.z; As[mm][kk+3] = v.w;
        }
        {   // NT load of Y
            int nn = tid >> 2, kk = (tid & 3) << 2;
            float4 v = *(const float4*)(Bb + (long)(n0 + nn) * Dn + k0 + kk);
            Bs[kk][nn] = v.x; Bs[kk+1][nn] = v.y; Bs[kk+2][nn] = v.z; Bs[kk+3][nn] = v.w;
        }
        __syncthreads();
        #pragma unroll
        for (int kk = 0; kk < 16; kk++) {
            float a[4], b[4];
            #pragma unroll
            for (int r = 0; r < 4; r++) a[r] = As[ty*4 + r][kk];
            #pragma unroll
            for (int c = 0; c < 4; c++) b[c] = Bs[kk][tx + 16*c];
            #pragma unroll
            for (int r = 0; r < 4; r++)
                #pragma unroll
                for (int c = 0; c < 4; c++) acc[r][c] = fmaf(a[r], b[c], acc[r][c]);
        }
        __syncthreads();
    }
    // stage C tile
    #pragma unroll
    for (int r = 0; r < 4; r++)
        #pragma unroll
        for (int c = 0; c < 4; c++)
            Cs[ty*4 + r][tx + 16*c] = acc[r][c];
    __syncthreads();

    const int colw = tid & 63, roww = tid >> 6;
    if (!sym) {
        #pragma unroll
        for (int i = 0; i < 16; i++) {
            int r = roww + i*4;
            Ob[(long)(m0 + r) * Sn + n0 + colw] = Cs[r][colw];
        }
    } else if (bx < by) {
        #pragma unroll
        for (int i = 0; i < 16; i++) {
            int r = roww + i*4;
            Ob[(long)(m0 + r) * Sn + n0 + colw] = Cs[r][colw];        // upper
            Ob[(long)(n0 + r) * Sn + m0 + colw] = Cs[colw][r];        // mirrored lower
        }
    } else {  // diagonal tile: select within tile
        #pragma unroll
        for (int i = 0; i < 16; i++) {
            int r = roww + i*4;
            Ob[(long)(m0 + r) * Sn + n0 + colw] = (r <= colw) ? Cs[r][colw] : Cs[colw][r];
        }
    }
}

// ============================================================================
// pt_cop mirror pass over output layout [b,x,y,z]: for x>y, out[b,x,y,:] = out[b,y,x,:]
// ============================================================================
__global__ void mirror_kernel(float* __restrict__ Out)
{
    const int x = blockIdx.x, b = blockIdx.y;
    for (int y = 0; y < x; y++) {
        long dst = ((long)(b * Sn + x) * Sn + y) * Sn;
        long src = ((long)(b * Sn + y) * Sn + x) * Sn;
        for (int z = threadIdx.x; z < Sn; z += blockDim.x)
            Out[dst + z] = Out[src + z];
    }
}

// ============================================================================
extern "C" void kernel_launch(void* const* d_in, const int* in_sizes, int n_in,
                              void* d_out, int out_size)
{
    const float* x  = (const float*)d_in[0];
    const float* Wp = (const float*)d_in[1];
    const float* bp = (const float*)d_in[2];
    const float* Wh = (const float*)d_in[3];
    const float* bh = (const float*)d_in[4];
    const float* Wt = (const float*)d_in[5];
    const float* bt = (const float*)d_in[6];
    const float* W_span_ph = (const float*)d_in[7];
    const float* W_span_pt = (const float*)d_in[8];
    const float* W_ph_sib  = (const float*)d_in[9];
    const float* W_pt_sib  = (const float*)d_in[10];
    const float* W_ph_cop  = (const float*)d_in[11];
    const float* W_pt_cop  = (const float*)d_in[12];
    float* out = (float*)d_out;

    float *mlpP, *wzP, *tP;
    cudaGetSymbolAddress((void**)&mlpP, g_mlp);
    cudaGetSymbolAddress((void**)&wzP,  g_wz);
    cudaGetSymbolAddress((void**)&tP,   g_t);
    const float* p  = mlpP;
    const float* sh = mlpP + BSn * Dn;
    const float* st = mlpP + 2 * BSn * Dn;

    // p, sh, st
    mlp_kernel<<<dim3(6, 2, 3), 256>>>(x, Wp, bp, Wh, bh, Wt, bt);

    // ---- type 1 (sym, layout [b,z,x,y]): span_psh, span_pst, ph_sib, pt_sib ----
    const float* Ws1[4] = {W_span_ph, W_span_pt, W_ph_sib, W_pt_sib};
    const float* Xs1[4] = {sh, sh, sh, st};
    const float* Ys1[4] = {st, st, sh, st};
    for (int t = 0; t < 4; t++) {
        // wz[r, i, j] = sum_k p[r,k] * w[i,k,j]   (batch over i)
        gemm_kernel<<<dim3(6, 2, 128), 256>>>(p, Ws1[t], wzP,
            Dn, Dn, Dn*Dn, 1, 0L, (long)Dn*Dn, (long)Dn, 0);
        // t[q, x, j] = sum_i X[b,x,i] * wz[q,i,j]  (NN, batch over q=(b,z))
        gemm_kernel<<<dim3(3, 2, 384), 256>>>(Xs1[t], wzP, tP,
            Dn, Dn, Dn, Sn, (long)Sn*Dn, (long)Dn*Dn, (long)Sn*Dn, 0);
        // s[q, x, y] = sum_j t[q,x,j] * Y[b,y,j]   (NT, symmetrized write)
        gemm_out_kernel<<<dim3(3, 3, 384), 256>>>(tP, Ys1[t], out + (long)t * SZo, 1);
    }

    // ---- type 2 (co-parent, layout [b,x,y,z]): ph_cop, pt_cop ----
    const float* Ws2[2] = {W_ph_cop, W_pt_cop};
    const float* Zs2[2] = {sh, st};
    for (int t = 0; t < 2; t++) {
        // u[r, k, j] = sum_i p[r,i] * w[i,k,j]    (batch over k)
        gemm_kernel<<<dim3(6, 2, 128), 256>>>(p, Ws2[t], wzP,
            Dn, Dn*Dn, Dn*Dn, 1, 0L, (long)Dn, (long)Dn, 0);
        // v[q, y, k] = sum_j p[b,y,j] * u[q,k,j]  (NT, batch over q=(b,x))
        gemm_kernel<<<dim3(3, 2, 384), 256>>>(p, wzP, tP,
            Dn, Dn, Dn, Sn, (long)Sn*Dn, (long)Dn*Dn, (long)Sn*Dn, 1);
        // out[q, y, z] = sum_k v[q,y,k] * Z[b,z,k] (NT, full write, z contiguous)
        gemm_out_kernel<<<dim3(3, 3, 384), 256>>>(tP, Zs2[t], out + (long)(4 + t) * SZo, 0);
    }
    // pt_cop: sym over (x,y) crosses batch planes -> mirror pass
    mirror_kernel<<<dim3(Sn, Bn), 192>>>(out + 5 * SZo);
}

// round 5
// speedup vs baseline: 1.0010x; 1.0010x over previous
#include <cuda_runtime.h>

#define Bn  2
#define Sn  192
#define Dn  128
#define DIN 1024
#define BSn (Bn*Sn)                       // 384 rows
#define SZo ((long)Bn*Sn*Sn*Sn)           // 14,155,776 elements per output tensor

// ---- scratch (device globals: allocation-free contract) ----
__device__ float g_mlp[3*BSn*Dn];         // p, sh, st        (576 KB)
__device__ float g_wz[BSn*Dn*Dn];         // wz / u scratch   (25.2 MB)
__device__ float g_t [BSn*Sn*Dn];         // t  / v scratch   (37.7 MB)

// ============================================================================
// MLP: C = leaky_relu(x @ W + b), 64x64 tiles, K=1024. grid(6,2,3)
// ============================================================================
__global__ __launch_bounds__(256) void mlp_kernel(
    const float* __restrict__ x,
    const float* __restrict__ W0, const float* __restrict__ b0,
    const float* __restrict__ W1, const float* __restrict__ b1,
    const float* __restrict__ W2, const float* __restrict__ b2)
{
    const int mt = blockIdx.x, nt = blockIdx.y, w = blockIdx.z;
    const float* W    = (w == 0) ? W0 : (w == 1) ? W1 : W2;
    const float* bias = (w == 0) ? b0 : (w == 1) ? b1 : b2;
    float* C = g_mlp + (long)w * BSn * Dn;

    __shared__ float As[64][17];
    __shared__ float Bs[16][65];
    const int tid = threadIdx.x;
    const int tx = tid & 15, ty = tid >> 4;
    const int m0 = mt * 64, n0 = nt * 64;
    float acc[4][4] = {};

    for (int k0 = 0; k0 < DIN; k0 += 16) {
        {   // A tile [64 x 16]
            int mm = tid >> 2, kk = (tid & 3) << 2;
            float4 v = *(const float4*)(x + (long)(m0 + mm) * DIN + k0 + kk);
            As[mm][kk] = v.x; As[mm][kk+1] = v.y; As[mm][kk+2] = v.z; As[mm][kk+3] = v.w;
        }
        {   // B tile [16 x 64] (NN)
            int kk = tid >> 4, nn = (tid & 15) << 2;
            float4 v = *(const float4*)(W + (long)(k0 + kk) * Dn + n0 + nn);
            Bs[kk][nn] = v.x; Bs[kk][nn+1] = v.y; Bs[kk][nn+2] = v.z; Bs[kk][nn+3] = v.w;
        }
        __syncthreads();
        #pragma unroll
        for (int kk = 0; kk < 16; kk++) {
            float a[4], b[4];
            #pragma unroll
            for (int r = 0; r < 4; r++) a[r] = As[ty*4 + r][kk];
            #pragma unroll
            for (int c = 0; c < 4; c++) b[c] = Bs[kk][tx + 16*c];
            #pragma unroll
            for (int r = 0; r < 4; r++)
                #pragma unroll
                for (int c = 0; c < 4; c++) acc[r][c] = fmaf(a[r], b[c], acc[r][c]);
        }
        __syncthreads();
    }
    #pragma unroll
    for (int r = 0; r < 4; r++) {
        int m = m0 + ty*4 + r;
        #pragma unroll
        for (int c = 0; c < 4; c++) {
            int n = n0 + tx + 16*c;
            float v = acc[r][c] + bias[n];
            v = (v > 0.f) ? v : 0.1f * v;
            C[(long)m * Dn + n] = v;
        }
    }
}

// ============================================================================
// Generic batched GEMM: C[m,n] = sum_c A[m,c] * B[m? n,c or c,n]
//   grid: (M/64, N/64, batch).  K fixed = 128.
//   A base = A + (z / aDiv) * aStride ; B base = B + z * bStride ; C base = C + z * cStride
//   bT = 0 : NN  (B[c*ldb + n]),  bT = 1 : NT  (B[n*ldb + c])
// ============================================================================
__global__ __launch_bounds__(256) void gemm_kernel(
    const float* __restrict__ A, const float* __restrict__ Bm, float* __restrict__ C,
    int lda, int ldb, int ldc,
    int aDiv, long aStride, long bStride, long cStride, int bT)
{
    const int mt = blockIdx.x, nt = blockIdx.y, z = blockIdx.z;
    const float* Ab = A + (long)(z / aDiv) * aStride;
    const float* Bb = Bm + (long)z * bStride;
    float* Cb = C + (long)z * cStride;
    const int m0 = mt * 64, n0 = nt * 64;

    __shared__ float As[64][17];
    __shared__ float Bs[16][65];
    const int tid = threadIdx.x;
    const int tx = tid & 15, ty = tid >> 4;
    float acc[4][4] = {};

    for (int k0 = 0; k0 < 128; k0 += 16) {
        {
            int mm = tid >> 2, kk = (tid & 3) << 2;
            float4 v = *(const float4*)(Ab + (long)(m0 + mm) * lda + k0 + kk);
            As[mm][kk] = v.x; As[mm][kk+1] = v.y; As[mm][kk+2] = v.z; As[mm][kk+3] = v.w;
        }
        if (!bT) {
            int kk = tid >> 4, nn = (tid & 15) << 2;
            float4 v = *(const float4*)(Bb + (long)(k0 + kk) * ldb + n0 + nn);
            Bs[kk][nn] = v.x; Bs[kk][nn+1] = v.y; Bs[kk][nn+2] = v.z; Bs[kk][nn+3] = v.w;
        } else {
            int nn = tid >> 2, kk = (tid & 3) << 2;
            float4 v = *(const float4*)(Bb + (long)(n0 + nn) * ldb + k0 + kk);
            Bs[kk][nn] = v.x; Bs[kk+1][nn] = v.y; Bs[kk+2][nn] = v.z; Bs[kk+3][nn] = v.w;
        }
        __syncthreads();
        #pragma unroll
        for (int kk = 0; kk < 16; kk++) {
            float a[4], b[4];
            #pragma unroll
            for (int r = 0; r < 4; r++) a[r] = As[ty*4 + r][kk];
            #pragma unroll
            for (int c = 0; c < 4; c++) b[c] = Bs[kk][tx + 16*c];
            #pragma unroll
            for (int r = 0; r < 4; r++)
                #pragma unroll
                for (int c = 0; c < 4; c++) acc[r][c] = fmaf(a[r], b[c], acc[r][c]);
        }
        __syncthreads();
    }
    #pragma unroll
    for (int r = 0; r < 4; r++) {
        int m = m0 + ty*4 + r;
        #pragma unroll
        for (int c = 0; c < 4; c++)
            Cb[(long)m * ldc + n0 + tx + 16*c] = acc[r][c];
    }
}

// ============================================================================
// Output GEMM (stage B2): s[q][m,n] = sum_k A[q][m,k] * Y[b][n,k]   (NT)
//   M = N = Sn, K = 128, batch q in [0, BSn). Writes to Out + q*Sn*Sn.
//   sym = 1: compute only upper tiles, write value + mirror (triu + triu(1).T)
//   sym = 0: full write.
// ============================================================================
__global__ __launch_bounds__(256) void gemm_out_kernel(
    const float* __restrict__ A, const float* __restrict__ Y,
    float* __restrict__ Out, int sym)
{
    const int bx = blockIdx.x, by = blockIdx.y, q = blockIdx.z;
    if (sym && bx > by) return;
    const float* Ab = A + (long)q * (Sn * Dn);
    const float* Bb = Y + (long)(q / Sn) * (Sn * Dn);
    float* Ob = Out + (long)q * (Sn * Sn);
    const int m0 = bx * 64, n0 = by * 64;

    __shared__ float As[64][17];
    __shared__ float Bs[16][65];
    __shared__ float Cs[64][65];
    const int tid = threadIdx.x;
    const int tx = tid & 15, ty = tid >> 4;
    float acc[4][4] = {};

    for (int k0 = 0; k0 < 128; k0 += 16) {
        {
            int mm = tid >> 2, kk = (tid & 3) << 2;
            float4 v = *(const float4*)(Ab + (long)(m0 + mm) * Dn + k0 + kk);
            As[mm][kk] = v.x; As[mm][kk+1] = v.y; As[mm][kk+2] = v.z; As[mm][kk+3] = v.w;
        }
        {   // NT load of Y
            int nn = tid >> 2, kk = (tid & 3) << 2;
            float4 v = *(const float4*)(Bb + (long)(n0 + nn) * Dn + k0 + kk);
            Bs[kk][nn] = v.x; Bs[kk+1][nn] = v.y; Bs[kk+2][nn] = v.z; Bs[kk+3][nn] = v.w;
        }
        __syncthreads();
        #pragma unroll
        for (int kk = 0; kk < 16; kk++) {
            float a[4], b[4];
            #pragma unroll
            for (int r = 0; r < 4; r++) a[r] = As[ty*4 + r][kk];
            #pragma unroll
            for (int c = 0; c < 4; c++) b[c] = Bs[kk][tx + 16*c];
            #pragma unroll
            for (int r = 0; r < 4; r++)
                #pragma unroll
                for (int c = 0; c < 4; c++) acc[r][c] = fmaf(a[r], b[c], acc[r][c]);
        }
        __syncthreads();
    }
    // stage C tile
    #pragma unroll
    for (int r = 0; r < 4; r++)
        #pragma unroll
        for (int c = 0; c < 4; c++)
            Cs[ty*4 + r][tx + 16*c] = acc[r][c];
    __syncthreads();

    const int colw = tid & 63, roww = tid >> 6;
    if (!sym) {
        #pragma unroll
        for (int i = 0; i < 16; i++) {
            int r = roww + i*4;
            Ob[(long)(m0 + r) * Sn + n0 + colw] = Cs[r][colw];
        }
    } else if (bx < by) {
        #pragma unroll
        for (int i = 0; i < 16; i++) {
            int r = roww + i*4;
            Ob[(long)(m0 + r) * Sn + n0 + colw] = Cs[r][colw];        // upper
            Ob[(long)(n0 + r) * Sn + m0 + colw] = Cs[colw][r];        // mirrored lower
        }
    } else {  // diagonal tile: select within tile
        #pragma unroll
        for (int i = 0; i < 16; i++) {
            int r = roww + i*4;
            Ob[(long)(m0 + r) * Sn + n0 + colw] = (r <= colw) ? Cs[r][colw] : Cs[colw][r];
        }
    }
}

// ============================================================================
// pt_cop mirror pass over output layout [b,x,y,z]: for x>y, out[b,x,y,:] = out[b,y,x,:]
// ============================================================================
__global__ void mirror_kernel(float* __restrict__ Out)
{
    const int x = blockIdx.x, b = blockIdx.y;
    for (int y = 0; y < x; y++) {
        long dst = ((long)(b * Sn + x) * Sn + y) * Sn;
        long src = ((long)(b * Sn + y) * Sn + x) * Sn;
        for (int z = threadIdx.x; z < Sn; z += blockDim.x)
            Out[dst + z] = Out[src + z];
    }
}

// ============================================================================
extern "C" void kernel_launch(void* const* d_in, const int* in_sizes, int n_in,
                              void* d_out, int out_size)
{
    const float* x  = (const float*)d_in[0];
    const float* Wp = (const float*)d_in[1];
    const float* bp = (const float*)d_in[2];
    const float* Wh = (const float*)d_in[3];
    const float* bh = (const float*)d_in[4];
    const float* Wt = (const float*)d_in[5];
    const float* bt = (const float*)d_in[6];
    const float* W_span_ph = (const float*)d_in[7];
    const float* W_span_pt = (const float*)d_in[8];
    const float* W_ph_sib  = (const float*)d_in[9];
    const float* W_pt_sib  = (const float*)d_in[10];
    const float* W_ph_cop  = (const float*)d_in[11];
    const float* W_pt_cop  = (const float*)d_in[12];
    float* out = (float*)d_out;

    float *mlpP, *wzP, *tP;
    cudaGetSymbolAddress((void**)&mlpP, g_mlp);
    cudaGetSymbolAddress((void**)&wzP,  g_wz);
    cudaGetSymbolAddress((void**)&tP,   g_t);
    const float* p  = mlpP;
    const float* sh = mlpP + BSn * Dn;
    const float* st = mlpP + 2 * BSn * Dn;

    // p, sh, st
    mlp_kernel<<<dim3(6, 2, 3), 256>>>(x, Wp, bp, Wh, bh, Wt, bt);

    // ---- type 1 (sym, layout [b,z,x,y]): span_psh, span_pst, ph_sib, pt_sib ----
    const float* Ws1[4] = {W_span_ph, W_span_pt, W_ph_sib, W_pt_sib};
    const float* Xs1[4] = {sh, sh, sh, st};
    const float* Ys1[4] = {st, st, sh, st};
    for (int t = 0; t < 4; t++) {
        // wz[r, i, j] = sum_k p[r,k] * w[i,k,j]   (batch over i)
        gemm_kernel<<<dim3(6, 2, 128), 256>>>(p, Ws1[t], wzP,
            Dn, Dn, Dn*Dn, 1, 0L, (long)Dn*Dn, (long)Dn, 0);
        // t[q, x, j] = sum_i X[b,x,i] * wz[q,i,j]  (NN, batch over q=(b,z))
        gemm_kernel<<<dim3(3, 2, 384), 256>>>(Xs1[t], wzP, tP,
            Dn, Dn, Dn, Sn, (long)Sn*Dn, (long)Dn*Dn, (long)Sn*Dn, 0);
        // s[q, x, y] = sum_j t[q,x,j] * Y[b,y,j]   (NT, symmetrized write)
        gemm_out_kernel<<<dim3(3, 3, 384), 256>>>(tP, Ys1[t], out + (long)t * SZo, 1);
    }

    // ---- type 2 (co-parent, layout [b,x,y,z]): ph_cop, pt_cop ----
    const float* Ws2[2] = {W_ph_cop, W_pt_cop};
    const float* Zs2[2] = {sh, st};
    for (int t = 0; t < 2; t++) {
        // u[r, k, j] = sum_i p[r,i] * w[i,k,j]    (batch over k)
        gemm_kernel<<<dim3(6, 2, 128), 256>>>(p, Ws2[t], wzP,
            Dn, Dn*Dn, Dn*Dn, 1, 0L, (long)Dn, (long)Dn, 0);
        // v[q, y, k] = sum_j p[b,y,j] * u[q,k,j]  (NT, batch over q=(b,x))
        gemm_kernel<<<dim3(3, 2, 384), 256>>>(p, wzP, tP,
            Dn, Dn, Dn, Sn, (long)Sn*Dn, (long)Dn*Dn, (long)Sn*Dn, 1);
        // out[q, y, z] = sum_k v[q,y,k] * Z[b,z,k] (NT, full write, z contiguous)
        gemm_out_kernel<<<dim3(3, 3, 384), 256>>>(tP, Zs2[t], out + (long)(4 + t) * SZo, 0);
    }
    // pt_cop: sym over (x,y) crosses batch planes -> mirror pass
    mirror_kernel<<<dim3(Sn, Bn), 192>>>(out + 5 * SZo);
}

// round 9
// speedup vs baseline: 1.0014x; 1.0003x over previous
#include <cuda_runtime.h>

#define Bn  2
#define Sn  192
#define Dn  128
#define DIN 1024
#define BSn (Bn*Sn)                       // 384 rows
#define SZo ((long)Bn*Sn*Sn*Sn)           // 14,155,776 elements per output tensor

// ---- scratch (device globals: allocation-free contract) ----
__device__ float g_mlp[3*BSn*Dn];         // p, sh, st        (576 KB)
__device__ float g_wz[BSn*Dn*Dn];         // wz / u scratch   (25.2 MB)
__device__ float g_t [BSn*Sn*Dn];         // t  / v scratch   (37.7 MB)

// ============================================================================
// MLP: C = leaky_relu(x @ W + b), 64x64 tiles, K=1024. grid(6,2,3)
// ============================================================================
__global__ __launch_bounds__(256) void mlp_kernel(
    const float* __restrict__ x,
    const float* __restrict__ W0, const float* __restrict__ b0,
    const float* __restrict__ W1, const float* __restrict__ b1,
    const float* __restrict__ W2, const float* __restrict__ b2)
{
    const int mt = blockIdx.x, nt = blockIdx.y, w = blockIdx.z;
    const float* W    = (w == 0) ? W0 : (w == 1) ? W1 : W2;
    const float* bias = (w == 0) ? b0 : (w == 1) ? b1 : b2;
    float* C = g_mlp + (long)w * BSn * Dn;

    __shared__ float As[64][17];
    __shared__ float Bs[16][65];
    const int tid = threadIdx.x;
    const int tx = tid & 15, ty = tid >> 4;
    const int m0 = mt * 64, n0 = nt * 64;
    float acc[4][4] = {};

    for (int k0 = 0; k0 < DIN; k0 += 16) {
        {   // A tile [64 x 16]
            int mm = tid >> 2, kk = (tid & 3) << 2;
            float4 v = *(const float4*)(x + (long)(m0 + mm) * DIN + k0 + kk);
            As[mm][kk] = v.x; As[mm][kk+1] = v.y; As[mm][kk+2] = v.z; As[mm][kk+3] = v.w;
        }
        {   // B tile [16 x 64] (NN)
            int kk = tid >> 4, nn = (tid & 15) << 2;
            float4 v = *(const float4*)(W + (long)(k0 + kk) * Dn + n0 + nn);
            Bs[kk][nn] = v.x; Bs[kk][nn+1] = v.y; Bs[kk][nn+2] = v.z; Bs[kk][nn+3] = v.w;
        }
        __syncthreads();
        #pragma unroll
        for (int kk = 0; kk < 16; kk++) {
            float a[4], b[4];
            #pragma unroll
            for (int r = 0; r < 4; r++) a[r] = As[ty*4 + r][kk];
            #pragma unroll
            for (int c = 0; c < 4; c++) b[c] = Bs[kk][tx + 16*c];
            #pragma unroll
            for (int r = 0; r < 4; r++)
                #pragma unroll
                for (int c = 0; c < 4; c++) acc[r][c] = fmaf(a[r], b[c], acc[r][c]);
        }
        __syncthreads();
    }
    #pragma unroll
    for (int r = 0; r < 4; r++) {
        int m = m0 + ty*4 + r;
        #pragma unroll
        for (int c = 0; c < 4; c++) {
            int n = n0 + tx + 16*c;
            float v = acc[r][c] + bias[n];
            v = (v > 0.f) ? v : 0.1f * v;
            C[(long)m * Dn + n] = v;
        }
    }
}

// ============================================================================
// Generic batched GEMM: C[m,n] = sum_c A[m,c] * B[m? n,c or c,n]
//   grid: (M/64, N/64, batch).  K fixed = 128.
//   A base = A + (z / aDiv) * aStride ; B base = B + z * bStride ; C base = C + z * cStride
//   bT = 0 : NN  (B[c*ldb + n]),  bT = 1 : NT  (B[n*ldb + c])
// ============================================================================
__global__ __launch_bounds__(256) void gemm_kernel(
    const float* __restrict__ A, const float* __restrict__ Bm, float* __restrict__ C,
    int lda, int ldb, int ldc,
    int aDiv, long aStride, long bStride, long cStride, int bT)
{
    const int mt = blockIdx.x, nt = blockIdx.y, z = blockIdx.z;
    const float* Ab = A + (long)(z / aDiv) * aStride;
    const float* Bb = Bm + (long)z * bStride;
    float* Cb = C + (long)z * cStride;
    const int m0 = mt * 64, n0 = nt * 64;

    __shared__ float As[64][17];
    __shared__ float Bs[16][65];
    const int tid = threadIdx.x;
    const int tx = tid & 15, ty = tid >> 4;
    float acc[4][4] = {};

    for (int k0 = 0; k0 < 128; k0 += 16) {
        {
            int mm = tid >> 2, kk = (tid & 3) << 2;
            float4 v = *(const float4*)(Ab + (long)(m0 + mm) * lda + k0 + kk);
            As[mm][kk] = v.x; As[mm][kk+1] = v.y; As[mm][kk+2] = v.z; As[mm][kk+3] = v.w;
        }
        if (!bT) {
            int kk = tid >> 4, nn = (tid & 15) << 2;
            float4 v = *(const float4*)(Bb + (long)(k0 + kk) * ldb + n0 + nn);
            Bs[kk][nn] = v.x; Bs[kk][nn+1] = v.y; Bs[kk][nn+2] = v.z; Bs[kk][nn+3] = v.w;
        } else {
            int nn = tid >> 2, kk = (tid & 3) << 2;
            float4 v = *(const float4*)(Bb + (long)(n0 + nn) * ldb + k0 + kk);
            Bs[kk][nn] = v.x; Bs[kk+1][nn] = v.y; Bs[kk+2][nn] = v.z; Bs[kk+3][nn] = v.w;
        }
        __syncthreads();
        #pragma unroll
        for (int kk = 0; kk < 16; kk++) {
            float a[4], b[4];
            #pragma unroll
            for (int r = 0; r < 4; r++) a[r] = As[ty*4 + r][kk];
            #pragma unroll
            for (int c = 0; c < 4; c++) b[c] = Bs[kk][tx + 16*c];
            #pragma unroll
            for (int r = 0; r < 4; r++)
                #pragma unroll
                for (int c = 0; c < 4; c++) acc[r][c] = fmaf(a[r], b[c], acc[r][c]);
        }
        __syncthreads();
    }
    #pragma unroll
    for (int r = 0; r < 4; r++) {
        int m = m0 + ty*4 + r;
        #pragma unroll
        for (int c = 0; c < 4; c++)
            Cb[(long)m * ldc + n0 + tx + 16*c] = acc[r][c];
    }
}

// ============================================================================
// Output GEMM (stage B2): s[q][m,n] = sum_k A[q][m,k] * Y[b][n,k]   (NT)
//   M = N = Sn, K = 128, batch q in [0, BSn). Writes to Out + q*Sn*Sn.
//   sym = 1: compute only upper tiles, write value + mirror (triu + triu(1).T)
//   sym = 0: full write.
// ============================================================================
__global__ __launch_bounds__(256) void gemm_out_kernel(
    const float* __restrict__ A, const float* __restrict__ Y,
    float* __restrict__ Out, int sym)
{
    const int bx = blockIdx.x, by = blockIdx.y, q = blockIdx.z;
    if (sym && bx > by) return;
    const float* Ab = A + (long)q * (Sn * Dn);
    const float* Bb = Y + (long)(q / Sn) * (Sn * Dn);
    float* Ob = Out + (long)q * (Sn * Sn);
    const int m0 = bx * 64, n0 = by * 64;

    __shared__ float As[64][17];
    __shared__ float Bs[16][65];
    __shared__ float Cs[64][65];
    const int tid = threadIdx.x;
    const int tx = tid & 15, ty = tid >> 4;
    float acc[4][4] = {};

    for (int k0 = 0; k0 < 128; k0 += 16) {
        {
            int mm = tid >> 2, kk = (tid & 3) << 2;
            float4 v = *(const float4*)(Ab + (long)(m0 + mm) * Dn + k0 + kk);
            As[mm][kk] = v.x; As[mm][kk+1] = v.y; As[mm][kk+2] = v.z; As[mm][kk+3] = v.w;
        }
        {   // NT load of Y
            int nn = tid >> 2, kk = (tid & 3) << 2;
            float4 v = *(const float4*)(Bb + (long)(n0 + nn) * Dn + k0 + kk);
            Bs[kk][nn] = v.x; Bs[kk+1][nn] = v.y; Bs[kk+2][nn] = v.z; Bs[kk+3][nn] = v.w;
        }
        __syncthreads();
        #pragma unroll
        for (int kk = 0; kk < 16; kk++) {
            float a[4], b[4];
            #pragma unroll
            for (int r = 0; r < 4; r++) a[r] = As[ty*4 + r][kk];
            #pragma unroll
            for (int c = 0; c < 4; c++) b[c] = Bs[kk][tx + 16*c];
            #pragma unroll
            for (int r = 0; r < 4; r++)
                #pragma unroll
                for (int c = 0; c < 4; c++) acc[r][c] = fmaf(a[r], b[c], acc[r][c]);
        }
        __syncthreads();
    }
    // stage C tile
    #pragma unroll
    for (int r = 0; r < 4; r++)
        #pragma unroll
        for (int c = 0; c < 4; c++)
            Cs[ty*4 + r][tx + 16*c] = acc[r][c];
    __syncthreads();

    const int colw = tid & 63, roww = tid >> 6;
    if (!sym) {
        #pragma unroll
        for (int i = 0; i < 16; i++) {
            int r = roww + i*4;
            Ob[(long)(m0 + r) * Sn + n0 + colw] = Cs[r][colw];
        }
    } else if (bx < by) {
        #pragma unroll
        for (int i = 0; i < 16; i++) {
            int r = roww + i*4;
            Ob[(long)(m0 + r) * Sn + n0 + colw] = Cs[r][colw];        // upper
            Ob[(long)(n0 + r) * Sn + m0 + colw] = Cs[colw][r];        // mirrored lower
        }
    } else {  // diagonal tile: select within tile
        #pragma unroll
        for (int i = 0; i < 16; i++) {
            int r = roww + i*4;
            Ob[(long)(m0 + r) * Sn + n0 + colw] = (r <= colw) ? Cs[r][colw] : Cs[colw][r];
        }
    }
}

// ============================================================================
// pt_cop mirror pass over output layout [b,x,y,z]: for x>y, out[b,x,y,:] = out[b,y,x,:]
// ============================================================================
__global__ void mirror_kernel(float* __restrict__ Out)
{
    const int x = blockIdx.x, b = blockIdx.y;
    for (int y = 0; y < x; y++) {
        long dst = ((long)(b * Sn + x) * Sn + y) * Sn;
        long src = ((long)(b * Sn + y) * Sn + x) * Sn;
        for (int z = threadIdx.x; z < Sn; z += blockDim.x)
            Out[dst + z] = Out[src + z];
    }
}

// ============================================================================
extern "C" void kernel_launch(void* const* d_in, const int* in_sizes, int n_in,
                              void* d_out, int out_size)
{
    const float* x  = (const float*)d_in[0];
    const float* Wp = (const float*)d_in[1];
    const float* bp = (const float*)d_in[2];
    const float* Wh = (const float*)d_in[3];
    const float* bh = (const float*)d_in[4];
    const float* Wt = (const float*)d_in[5];
    const float* bt = (const float*)d_in[6];
    const float* W_span_ph = (const float*)d_in[7];
    const float* W_span_pt = (const float*)d_in[8];
    const float* W_ph_sib  = (const float*)d_in[9];
    const float* W_pt_sib  = (const float*)d_in[10];
    const float* W_ph_cop  = (const float*)d_in[11];
    const float* W_pt_cop  = (const float*)d_in[12];
    float* out = (float*)d_out;

    float *mlpP, *wzP, *tP;
    cudaGetSymbolAddress((void**)&mlpP, g_mlp);
    cudaGetSymbolAddress((void**)&wzP,  g_wz);
    cudaGetSymbolAddress((void**)&tP,   g_t);
    const float* p  = mlpP;
    const float* sh = mlpP + BSn * Dn;
    const float* st = mlpP + 2 * BSn * Dn;

    // p, sh, st
    mlp_kernel<<<dim3(6, 2, 3), 256>>>(x, Wp, bp, Wh, bh, Wt, bt);

    // ---- type 1 (sym, layout [b,z,x,y]): span_psh, span_pst, ph_sib, pt_sib ----
    const float* Ws1[4] = {W_span_ph, W_span_pt, W_ph_sib, W_pt_sib};
    const float* Xs1[4] = {sh, sh, sh, st};
    const float* Ys1[4] = {st, st, sh, st};
    for (int t = 0; t < 4; t++) {
        // wz[r, i, j] = sum_k p[r,k] * w[i,k,j]   (batch over i)
        gemm_kernel<<<dim3(6, 2, 128), 256>>>(p, Ws1[t], wzP,
            Dn, Dn, Dn*Dn, 1, 0L, (long)Dn*Dn, (long)Dn, 0);
        // t[q, x, j] = sum_i X[b,x,i] * wz[q,i,j]  (NN, batch over q=(b,z))
        gemm_kernel<<<dim3(3, 2, 384), 256>>>(Xs1[t], wzP, tP,
            Dn, Dn, Dn, Sn, (long)Sn*Dn, (long)Dn*Dn, (long)Sn*Dn, 0);
        // s[q, x, y] = sum_j t[q,x,j] * Y[b,y,j]   (NT, symmetrized write)
        gemm_out_kernel<<<dim3(3, 3, 384), 256>>>(tP, Ys1[t], out + (long)t * SZo, 1);
    }

    // ---- type 2 (co-parent, layout [b,x,y,z]): ph_cop, pt_cop ----
    const float* Ws2[2] = {W_ph_cop, W_pt_cop};
    const float* Zs2[2] = {sh, st};
    for (int t = 0; t < 2; t++) {
        // u[r, k, j] = sum_i p[r,i] * w[i,k,j]    (batch over k)
        gemm_kernel<<<dim3(6, 2, 128), 256>>>(p, Ws2[t], wzP,
            Dn, Dn*Dn, Dn*Dn, 1, 0L, (long)Dn, (long)Dn, 0);
        // v[q, y, k] = sum_j p[b,y,j] * u[q,k,j]  (NT, batch over q=(b,x))
        gemm_kernel<<<dim3(3, 2, 384), 256>>>(p, wzP, tP,
            Dn, Dn, Dn, Sn, (long)Sn*Dn, (long)Dn*Dn, (long)Sn*Dn, 1);
        // out[q, y, z] = sum_k v[q,y,k] * Z[b,z,k] (NT, full write, z contiguous)
        gemm_out_kernel<<<dim3(3, 3, 384), 256>>>(tP, Zs2[t], out + (long)(4 + t) * SZo, 0);
    }
    // pt_cop: sym over (x,y) crosses batch planes -> mirror pass
    mirror_kernel<<<dim3(Sn, Bn), 192>>>(out + 5 * SZo);
}